// round 3
// baseline (speedup 1.0000x reference)
#include <cuda_runtime.h>
#include <cuda_bf16.h>
#include <math.h>

#define TT  512
#define BB  64
#define DIN 256
#define NN  1024
#define OO  128

// ---------------- device scratch (no cudaMalloc allowed) ----------------
__device__ float    g_xw[(TT - 1) * NN * BB];   // [t][n][b], t = 0..510 feeds step t+1
__device__ float    g_sbuf[4 * NN * BB];        // 4-deep ring, transposed [n][b]
__device__ float    g_part[64 * 64 * 16];       // per-ntile k-half-0 partials (thread-mapped)
__device__ unsigned g_flag[64 * 8];             // per-ntile published-step flag (padded 32B)
__device__ unsigned g_pflag[64 * 8];            // per-ntile partial-ready step flag (padded)

// ---------------- acquire/release helpers ----------------
__device__ __forceinline__ unsigned ld_acq(const unsigned* p) {
    unsigned v;
    asm volatile("ld.acquire.gpu.u32 %0, [%1];" : "=r"(v) : "l"(p));
    return v;
}
__device__ __forceinline__ void st_rel(unsigned* p, unsigned v) {
    asm volatile("st.release.gpu.u32 [%0], %1;" :: "l"(p), "r"(v) : "memory");
}
__device__ __forceinline__ void wait_flag(const unsigned* p, unsigned tgt) {
    if (ld_acq(p) >= tgt) return;
    while (ld_acq(p) < tgt) __nanosleep(64);
}

// ---------------- init: reset sync state, zero s[:,0,:] ----------------
__global__ void init_kernel(float* __restrict__ sout) {
    int idx = blockIdx.x * blockDim.x + threadIdx.x;
    if (idx < 64 * 8) { g_flag[idx] = 0; g_pflag[idx] = 0; }
    if (idx < NN * BB) {
        g_sbuf[idx] = 0.0f;                          // ring slot 0 = state t=0
        int b = idx / NN, n = idx % NN;
        sout[((size_t)b * TT + 0) * NN + n] = 0.0f;  // s[:,0,:] = 0
    }
}

// ---------------- XW = X[:,t,:] @ Win, stored [t][n][b] ----------------
__global__ void xw_kernel(const float* __restrict__ X, const float* __restrict__ Win) {
    const int t  = blockIdx.x;          // 0..510
    const int c0 = blockIdx.y * 64;
    __shared__ float xs[16][BB];        // [d][b]
    __shared__ float ws[16][64];        // [d][c]
    const int tid = threadIdx.x;
    const int r0 = (tid & 15) * 4;
    const int cc = (tid >> 4) * 4;
    float acc[4][4] = {};

    for (int d0 = 0; d0 < DIN; d0 += 16) {
        {
            int b  = tid & 63;
            int d4 = (tid >> 6) * 4;
            float4 xv = *(const float4*)&X[((size_t)b * TT + t) * DIN + d0 + d4];
            xs[d4 + 0][b] = xv.x; xs[d4 + 1][b] = xv.y;
            xs[d4 + 2][b] = xv.z; xs[d4 + 3][b] = xv.w;
        }
        {
            int dr = tid >> 4;
            int c4 = (tid & 15) * 4;
            *(float4*)&ws[dr][c4] = *(const float4*)&Win[(size_t)(d0 + dr) * NN + c0 + c4];
        }
        __syncthreads();
        #pragma unroll
        for (int d = 0; d < 16; d++) {
            float4 a = *(const float4*)&xs[d][r0];
            float4 w = *(const float4*)&ws[d][cc];
            acc[0][0] += a.x * w.x; acc[0][1] += a.x * w.y; acc[0][2] += a.x * w.z; acc[0][3] += a.x * w.w;
            acc[1][0] += a.y * w.x; acc[1][1] += a.y * w.y; acc[1][2] += a.y * w.z; acc[1][3] += a.y * w.w;
            acc[2][0] += a.z * w.x; acc[2][1] += a.z * w.y; acc[2][2] += a.z * w.z; acc[2][3] += a.z * w.w;
            acc[3][0] += a.w * w.x; acc[3][1] += a.w * w.y; acc[3][2] += a.w * w.z; acc[3][3] += a.w * w.w;
        }
        __syncthreads();
    }
    #pragma unroll
    for (int j = 0; j < 4; j++) {
        float4 v = make_float4(acc[0][j], acc[1][j], acc[2][j], acc[3][j]);
        *(float4*)&g_xw[((size_t)t * NN + c0 + cc + j) * BB + r0] = v;
    }
}

// ---------------- persistent recurrence kernel (dataflow sync) ----------------
// 128 blocks x 128 threads. block = (ntile 0..63, khalf 0..1).
__global__ void __launch_bounds__(128, 1) rnn_kernel(const float* __restrict__ W,
                                                     float* __restrict__ sout) {
    const int bx    = blockIdx.x;
    const int ntile = bx >> 1;
    const int kh    = bx & 1;
    const int c0    = ntile * 16;
    const int kbase = kh * 512;
    const int ft    = kh * 32;          // first tile index of this k-half
    const int tid   = threadIdx.x;
    const int r0    = (tid & 15) * 4;   // b rows (4)
    const int cc    = (tid >> 4) * 2;   // local cols (2)

    __shared__ float ssm[2][32][BB];    // [buf][k][b]
    __shared__ float wsm[2][32][16];    // [buf][k][c]
    __shared__ float stage[64][20];     // [b][n_local], padded (80B rows, 16B aligned)

    const int wk = tid >> 2;            // W loader row 0..31
    const int wc = (tid & 3) * 4;       // W loader col group

    for (int t = 1; t < TT; t++) {
        const unsigned tgt = (unsigned)(t - 1);
        const float* __restrict__ sprev = &g_sbuf[((t - 1) & 3) * (NN * BB)];
        float acc[4][2] = {};

        // prologue: wait producers of chunk 0, load into buf 0
        wait_flag(&g_flag[(ft + 0) * 8], tgt);
        wait_flag(&g_flag[(ft + 1) * 8], tgt);
        {
            const float4* sv = (const float4*)(sprev + (size_t)kbase * BB);
            float4* d = (float4*)&ssm[0][0][0];
            #pragma unroll
            for (int i = 0; i < 4; i++) d[tid + 128 * i] = sv[tid + 128 * i];
            *(float4*)&wsm[0][wk][wc] = *(const float4*)&W[(size_t)(kbase + wk) * NN + c0 + wc];
        }
        __syncthreads();

        for (int kc = 0; kc < 16; kc++) {
            const int buf = kc & 1;
            float4 pfs[4]; float4 pfw;
            if (kc < 15) {
                wait_flag(&g_flag[(ft + 2 * (kc + 1) + 0) * 8], tgt);
                wait_flag(&g_flag[(ft + 2 * (kc + 1) + 1) * 8], tgt);
                const float4* sv = (const float4*)(sprev + (size_t)(kbase + (kc + 1) * 32) * BB);
                #pragma unroll
                for (int i = 0; i < 4; i++) pfs[i] = sv[tid + 128 * i];
                pfw = *(const float4*)&W[(size_t)(kbase + (kc + 1) * 32 + wk) * NN + c0 + wc];
            }
            const float (*sb)[BB] = ssm[buf];
            const float (*wb)[16] = wsm[buf];
            #pragma unroll
            for (int k = 0; k < 32; k++) {
                float4 sv = *(const float4*)&sb[k][r0];
                float2 wv = *(const float2*)&wb[k][cc];
                acc[0][0] += sv.x * wv.x; acc[0][1] += sv.x * wv.y;
                acc[1][0] += sv.y * wv.x; acc[1][1] += sv.y * wv.y;
                acc[2][0] += sv.z * wv.x; acc[2][1] += sv.z * wv.y;
                acc[3][0] += sv.w * wv.x; acc[3][1] += sv.w * wv.y;
            }
            if (kc < 15) {
                float4* d = (float4*)&ssm[buf ^ 1][0][0];
                #pragma unroll
                for (int i = 0; i < 4; i++) d[tid + 128 * i] = pfs[i];
                *(float4*)&wsm[buf ^ 1][wk][wc] = pfw;
                __syncthreads();
            }
        }

        float* p = &g_part[(size_t)ntile * 1024 + tid * 8];
        if (kh == 0) {
            // WAR: partner must have consumed step t-1 partials (flag[ntile] >= t-1)
            wait_flag(&g_flag[ntile * 8], tgt);
            *(float4*)&p[0] = make_float4(acc[0][0], acc[1][0], acc[2][0], acc[3][0]);
            *(float4*)&p[4] = make_float4(acc[0][1], acc[1][1], acc[2][1], acc[3][1]);
            __syncthreads();
            if (tid == 0) st_rel(&g_pflag[ntile * 8], (unsigned)t);
        } else {
            // wait for partner partials (per-thread acquire orders subsequent loads)
            wait_flag(&g_pflag[ntile * 8], (unsigned)t);
            float4 p0 = *(const float4*)&p[0];
            float4 p1 = *(const float4*)&p[4];
            const float* xwp = &g_xw[((size_t)(t - 1) * NN + c0 + cc) * BB];
            float4 x0 = *(const float4*)&xwp[0 * BB + r0];
            float4 x1 = *(const float4*)&xwp[1 * BB + r0];
            float sn[4][2];
            sn[0][0] = tanhf(acc[0][0] + p0.x + x0.x);
            sn[1][0] = tanhf(acc[1][0] + p0.y + x0.y);
            sn[2][0] = tanhf(acc[2][0] + p0.z + x0.z);
            sn[3][0] = tanhf(acc[3][0] + p0.w + x0.w);
            sn[0][1] = tanhf(acc[0][1] + p1.x + x1.x);
            sn[1][1] = tanhf(acc[1][1] + p1.y + x1.y);
            sn[2][1] = tanhf(acc[2][1] + p1.z + x1.z);
            sn[3][1] = tanhf(acc[3][1] + p1.w + x1.w);
            // state ring buffer (transposed [n][b])
            float* sb = &g_sbuf[(t & 3) * (NN * BB)];
            *(float4*)&sb[(size_t)(c0 + cc + 0) * BB + r0] =
                make_float4(sn[0][0], sn[1][0], sn[2][0], sn[3][0]);
            *(float4*)&sb[(size_t)(c0 + cc + 1) * BB + r0] =
                make_float4(sn[0][1], sn[1][1], sn[2][1], sn[3][1]);
            // stage into smem for coalesced sout write
            #pragma unroll
            for (int i = 0; i < 4; i++) {
                stage[r0 + i][cc + 0] = sn[i][0];
                stage[r0 + i][cc + 1] = sn[i][1];
            }
            __syncthreads();
            if (tid < 64) {
                float* dst = &sout[((size_t)tid * TT + t) * NN + c0];
                #pragma unroll
                for (int i = 0; i < 4; i++)
                    *(float4*)&dst[i * 4] = *(const float4*)&stage[tid][i * 4];
            }
            __syncthreads();
            if (tid == 0) st_rel(&g_flag[ntile * 8], (unsigned)t);
        }
    }
}

// ---------------- out = s @ Wout + bout ----------------
__global__ void out_kernel(const float* __restrict__ s, const float* __restrict__ Wout,
                           const float* __restrict__ bout, float* __restrict__ out) {
    const int m0 = blockIdx.x * 64;
    const int c0 = blockIdx.y * 64;
    __shared__ float as[16][64];        // [k][m]
    __shared__ float ws[16][64];        // [k][o]
    const int tid = threadIdx.x;
    const int r0 = (tid & 15) * 4;
    const int cc = (tid >> 4) * 4;
    float acc[4][4] = {};

    for (int k0 = 0; k0 < NN; k0 += 16) {
        {
            int m  = tid & 63;
            int k4 = (tid >> 6) * 4;
            float4 v = *(const float4*)&s[(size_t)(m0 + m) * NN + k0 + k4];
            as[k4 + 0][m] = v.x; as[k4 + 1][m] = v.y;
            as[k4 + 2][m] = v.z; as[k4 + 3][m] = v.w;
        }
        {
            int kr = tid >> 4;
            int c4 = (tid & 15) * 4;
            *(float4*)&ws[kr][c4] = *(const float4*)&Wout[(size_t)(k0 + kr) * OO + c0 + c4];
        }
        __syncthreads();
        #pragma unroll
        for (int k = 0; k < 16; k++) {
            float4 a = *(const float4*)&as[k][r0];
            float4 w = *(const float4*)&ws[k][cc];
            acc[0][0] += a.x * w.x; acc[0][1] += a.x * w.y; acc[0][2] += a.x * w.z; acc[0][3] += a.x * w.w;
            acc[1][0] += a.y * w.x; acc[1][1] += a.y * w.y; acc[1][2] += a.y * w.z; acc[1][3] += a.y * w.w;
            acc[2][0] += a.z * w.x; acc[2][1] += a.z * w.y; acc[2][2] += a.z * w.z; acc[2][3] += a.z * w.w;
            acc[3][0] += a.w * w.x; acc[3][1] += a.w * w.y; acc[3][2] += a.w * w.z; acc[3][3] += a.w * w.w;
        }
        __syncthreads();
    }
    float4 bv = *(const float4*)&bout[c0 + cc];
    #pragma unroll
    for (int i = 0; i < 4; i++) {
        float4 v = make_float4(acc[i][0] + bv.x, acc[i][1] + bv.y,
                               acc[i][2] + bv.z, acc[i][3] + bv.w);
        *(float4*)&out[(size_t)(m0 + r0 + i) * OO + c0 + cc] = v;
    }
}

// ---------------- launch ----------------
extern "C" void kernel_launch(void* const* d_in, const int* in_sizes, int n_in,
                              void* d_out, int out_size) {
    const float* X    = (const float*)d_in[0];  // [B,T,DIN]
    const float* Win  = (const float*)d_in[1];  // [DIN,N]
    const float* W    = (const float*)d_in[2];  // [N,N]
    const float* Wout = (const float*)d_in[3];  // [N,O]
    const float* bout = (const float*)d_in[4];  // [O]

    float* s_out = (float*)d_out;                            // [B,T,N]
    float* o_out = (float*)d_out + (size_t)BB * TT * NN;     // [B,T,O]

    init_kernel<<<256, 256>>>(s_out);
    xw_kernel<<<dim3(TT - 1, 16), 256>>>(X, Win);
    rnn_kernel<<<128, 128>>>(W, s_out);
    out_kernel<<<dim3((BB * TT) / 64, OO / 64), 256>>>(s_out, Wout, bout, o_out);
}

// round 6
// speedup vs baseline: 1.2423x; 1.2423x over previous
#include <cuda_runtime.h>
#include <cuda_bf16.h>
#include <math.h>

#define TT  512
#define BB  64
#define DIN 256
#define NN  1024
#define OO  128

// ---------------- device scratch (no cudaMalloc allowed) ----------------
__device__ float    g_xw[(TT - 1) * NN * BB];   // [t][n][b], t = 0..510 feeds step t+1
__device__ float    g_sbuf[4 * NN * BB];        // 4-deep ring, transposed [n][b]
__device__ float    g_part[64 * 64 * 16];       // per-ntile k-half-0 partials (thread-mapped)
__device__ unsigned g_bar;                      // barrier arrival counter (kh1 blocks only)
__device__ unsigned g_release;                  // last released step (monotonic per launch)
__device__ unsigned g_pflag[64 * 8];            // per-ntile partial-ready step flag (padded)

// ---------------- acquire/release helpers ----------------
__device__ __forceinline__ unsigned ld_acq(const unsigned* p) {
    unsigned v;
    asm volatile("ld.acquire.gpu.u32 %0, [%1];" : "=r"(v) : "l"(p));
    return v;
}
__device__ __forceinline__ void st_rel(unsigned* p, unsigned v) {
    asm volatile("st.release.gpu.u32 [%0], %1;" :: "l"(p), "r"(v) : "memory");
}
// bounded-backoff spin (monotonic flag -> cannot deadlock; backoff only cuts L2 traffic)
__device__ __forceinline__ void wait_ge(const unsigned* p, unsigned tgt) {
    #pragma unroll 1
    for (int i = 0; i < 16; i++) {
        if (ld_acq(p) >= tgt) return;
    }
    unsigned ns = 64;
    while (ld_acq(p) < tgt) {
        __nanosleep(ns);
        if (ns < 512) ns <<= 1;
    }
}

// packed fp32x2 FMA: d = a*b + d (lane-wise fp32, exact same numerics as FFMA)
__device__ __forceinline__ void ffma2(unsigned long long& d,
                                      unsigned long long a, unsigned long long b) {
    asm("fma.rn.f32x2 %0, %1, %2, %0;" : "+l"(d) : "l"(a), "l"(b));
}

// ---------------- init: reset sync state, zero s[:,0,:] ----------------
__global__ void init_kernel(float* __restrict__ sout) {
    int idx = blockIdx.x * blockDim.x + threadIdx.x;
    if (idx == 0) { g_bar = 0; g_release = 0; }
    if (idx < 64 * 8) g_pflag[idx] = 0;
    if (idx < NN * BB) {
        g_sbuf[idx] = 0.0f;                          // ring slot 0 = state t=0
        int b = idx / NN, n = idx % NN;
        sout[((size_t)b * TT + 0) * NN + n] = 0.0f;  // s[:,0,:] = 0
    }
}

// ---------------- XW = X[:,t,:] @ Win, stored [t][n][b] ----------------
__global__ void xw_kernel(const float* __restrict__ X, const float* __restrict__ Win) {
    const int t  = blockIdx.x;          // 0..510
    const int c0 = blockIdx.y * 64;
    __shared__ float xs[16][BB];        // [d][b]
    __shared__ float ws[16][64];        // [d][c]
    const int tid = threadIdx.x;
    const int r0 = (tid & 15) * 4;
    const int cc = (tid >> 4) * 4;
    float acc[4][4] = {};

    for (int d0 = 0; d0 < DIN; d0 += 16) {
        {
            int b  = tid & 63;
            int d4 = (tid >> 6) * 4;
            float4 xv = *(const float4*)&X[((size_t)b * TT + t) * DIN + d0 + d4];
            xs[d4 + 0][b] = xv.x; xs[d4 + 1][b] = xv.y;
            xs[d4 + 2][b] = xv.z; xs[d4 + 3][b] = xv.w;
        }
        {
            int dr = tid >> 4;
            int c4 = (tid & 15) * 4;
            *(float4*)&ws[dr][c4] = *(const float4*)&Win[(size_t)(d0 + dr) * NN + c0 + c4];
        }
        __syncthreads();
        #pragma unroll
        for (int d = 0; d < 16; d++) {
            float4 a = *(const float4*)&xs[d][r0];
            float4 w = *(const float4*)&ws[d][cc];
            acc[0][0] += a.x * w.x; acc[0][1] += a.x * w.y; acc[0][2] += a.x * w.z; acc[0][3] += a.x * w.w;
            acc[1][0] += a.y * w.x; acc[1][1] += a.y * w.y; acc[1][2] += a.y * w.z; acc[1][3] += a.y * w.w;
            acc[2][0] += a.z * w.x; acc[2][1] += a.z * w.y; acc[2][2] += a.z * w.z; acc[2][3] += a.z * w.w;
            acc[3][0] += a.w * w.x; acc[3][1] += a.w * w.y; acc[3][2] += a.w * w.z; acc[3][3] += a.w * w.w;
        }
        __syncthreads();
    }
    #pragma unroll
    for (int j = 0; j < 4; j++) {
        float4 v = make_float4(acc[0][j], acc[1][j], acc[2][j], acc[3][j]);
        *(float4*)&g_xw[((size_t)t * NN + c0 + cc + j) * BB + r0] = v;
    }
}

// ---------------- persistent recurrence kernel (R2 topology + FFMA2 core) ----------------
// 128 blocks x 128 threads. block = (ntile 0..63, khalf 0..1).
__global__ void __launch_bounds__(128, 1) rnn_kernel(const float* __restrict__ W,
                                                     float* __restrict__ sout) {
    const int bx    = blockIdx.x;
    const int ntile = bx >> 1;
    const int kh    = bx & 1;
    const int c0    = ntile * 16;
    const int kbase = kh * 512;
    const int tid   = threadIdx.x;
    const int r0    = (tid & 15) * 4;   // b rows (4)
    const int cc    = (tid >> 4) * 2;   // local cols (2)

    __shared__ float  ssm[2][32][BB];   // [buf][k][b]           16 KB
    __shared__ float2 wsm[2][32][16];   // [buf][k][c] dup (w,w)  8 KB
    __shared__ float  stage[64][20];    // [b][n_local], padded   5 KB

    const int wk = tid >> 2;            // W loader row 0..31
    const int wc = (tid & 3) * 4;       // W loader col group (4 cols -> 2 float4 dup stores)

    for (int t = 1; t < TT; t++) {
        const float* __restrict__ sprev = &g_sbuf[((t - 1) & 3) * (NN * BB)];
        unsigned long long ap0 = 0ull, ap1 = 0ull, ap2 = 0ull, ap3 = 0ull;
        // ap0=(r0,r0+1)@c0  ap1=(r0+2,r0+3)@c0  ap2=(r0,r0+1)@c1  ap3=(r0+2,r0+3)@c1

        // prologue: load chunk 0 into buf 0
        {
            const float4* sv = (const float4*)(sprev + (size_t)kbase * BB);
            float4* d = (float4*)&ssm[0][0][0];
            #pragma unroll
            for (int i = 0; i < 4; i++) d[tid + 128 * i] = sv[tid + 128 * i];
            float4 w = *(const float4*)&W[(size_t)(kbase + wk) * NN + c0 + wc];
            float* wd = (float*)&wsm[0][wk][wc];
            *(float4*)&wd[0] = make_float4(w.x, w.x, w.y, w.y);
            *(float4*)&wd[4] = make_float4(w.z, w.z, w.w, w.w);
        }
        __syncthreads();

        for (int kc = 0; kc < 16; kc++) {
            const int buf = kc & 1;
            float4 pfs[4]; float4 pfw;
            if (kc < 15) {
                const float4* sv = (const float4*)(sprev + (size_t)(kbase + (kc + 1) * 32) * BB);
                #pragma unroll
                for (int i = 0; i < 4; i++) pfs[i] = sv[tid + 128 * i];
                pfw = *(const float4*)&W[(size_t)(kbase + (kc + 1) * 32 + wk) * NN + c0 + wc];
            }
            const float  (*sb)[BB] = ssm[buf];
            const float2 (*wb)[16] = wsm[buf];
            #pragma unroll
            for (int k = 0; k < 32; k++) {
                ulonglong2 a = *(const ulonglong2*)&sb[k][r0];   // (s0,s1),(s2,s3)
                ulonglong2 b = *(const ulonglong2*)&wb[k][cc];   // (w0,w0),(w1,w1)
                ffma2(ap0, a.x, b.x);
                ffma2(ap1, a.y, b.x);
                ffma2(ap2, a.x, b.y);
                ffma2(ap3, a.y, b.y);
            }
            if (kc < 15) {
                float4* d = (float4*)&ssm[buf ^ 1][0][0];
                #pragma unroll
                for (int i = 0; i < 4; i++) d[tid + 128 * i] = pfs[i];
                float* wd = (float*)&wsm[buf ^ 1][wk][wc];
                *(float4*)&wd[0] = make_float4(pfw.x, pfw.x, pfw.y, pfw.y);
                *(float4*)&wd[4] = make_float4(pfw.z, pfw.z, pfw.w, pfw.w);
                __syncthreads();
            }
        }

        // unpack packed accumulators -> acc[row][col]
        float acc[4][2];
        {
            float2 u;
            u = *(float2*)&ap0; acc[0][0] = u.x; acc[1][0] = u.y;
            u = *(float2*)&ap1; acc[2][0] = u.x; acc[3][0] = u.y;
            u = *(float2*)&ap2; acc[0][1] = u.x; acc[1][1] = u.y;
            u = *(float2*)&ap3; acc[2][1] = u.x; acc[3][1] = u.y;
        }

        float* p = &g_part[(size_t)ntile * 1024 + tid * 8];
        if (kh == 0) {
            // (WAR on g_part is safe: we passed release >= t-1, which required our
            //  partner to have consumed step t-1 partials.)
            *(float4*)&p[0] = make_float4(acc[0][0], acc[1][0], acc[2][0], acc[3][0]);
            *(float4*)&p[4] = make_float4(acc[0][1], acc[1][1], acc[2][1], acc[3][1]);
            __threadfence();
            __syncthreads();
            if (tid == 0) st_rel(&g_pflag[ntile * 8], (unsigned)t);
        } else {
            if (tid == 0) wait_ge(&g_pflag[ntile * 8], (unsigned)t);
            __syncthreads();
            float4 p0 = *(const float4*)&p[0];
            float4 p1 = *(const float4*)&p[4];
            const float* xwp = &g_xw[((size_t)(t - 1) * NN + c0 + cc) * BB];
            float4 x0 = *(const float4*)&xwp[0 * BB + r0];
            float4 x1 = *(const float4*)&xwp[1 * BB + r0];
            float sn[4][2];
            sn[0][0] = tanhf(acc[0][0] + p0.x + x0.x);
            sn[1][0] = tanhf(acc[1][0] + p0.y + x0.y);
            sn[2][0] = tanhf(acc[2][0] + p0.z + x0.z);
            sn[3][0] = tanhf(acc[3][0] + p0.w + x0.w);
            sn[0][1] = tanhf(acc[0][1] + p1.x + x1.x);
            sn[1][1] = tanhf(acc[1][1] + p1.y + x1.y);
            sn[2][1] = tanhf(acc[2][1] + p1.z + x1.z);
            sn[3][1] = tanhf(acc[3][1] + p1.w + x1.w);
            // state ring buffer (transposed [n][b])
            float* sb = &g_sbuf[(t & 3) * (NN * BB)];
            *(float4*)&sb[(size_t)(c0 + cc + 0) * BB + r0] =
                make_float4(sn[0][0], sn[1][0], sn[2][0], sn[3][0]);
            *(float4*)&sb[(size_t)(c0 + cc + 1) * BB + r0] =
                make_float4(sn[0][1], sn[1][1], sn[2][1], sn[3][1]);
            // stage into smem for coalesced sout write
            #pragma unroll
            for (int i = 0; i < 4; i++) {
                stage[r0 + i][cc + 0] = sn[i][0];
                stage[r0 + i][cc + 1] = sn[i][1];
            }
            __syncthreads();
            if (tid < 64) {
                float* dst = &sout[((size_t)tid * TT + t) * NN + c0];
                #pragma unroll
                for (int i = 0; i < 4; i++)
                    *(float4*)&dst[i * 4] = *(const float4*)&stage[tid][i * 4];
            }
            __threadfence();
            __syncthreads();
        }

        // global step barrier: only kh1 blocks arrive (64 arrivals/step); all wait release
        if (tid == 0) {
            if (kh == 1) {
                unsigned v = atomicAdd(&g_bar, 1u) + 1u;
                if (v == (unsigned)(64 * t)) {
                    __threadfence();
                    st_rel(&g_release, (unsigned)t);
                }
            }
            wait_ge(&g_release, (unsigned)t);
        }
        __syncthreads();
    }
}

// ---------------- out = s @ Wout + bout ----------------
__global__ void out_kernel(const float* __restrict__ s, const float* __restrict__ Wout,
                           const float* __restrict__ bout, float* __restrict__ out) {
    const int m0 = blockIdx.x * 64;
    const int c0 = blockIdx.y * 64;
    __shared__ float as[16][64];        // [k][m]
    __shared__ float ws[16][64];        // [k][o]
    const int tid = threadIdx.x;
    const int r0 = (tid & 15) * 4;
    const int cc = (tid >> 4) * 4;
    float acc[4][4] = {};

    for (int k0 = 0; k0 < NN; k0 += 16) {
        {
            int m  = tid & 63;
            int k4 = (tid >> 6) * 4;
            float4 v = *(const float4*)&s[(size_t)(m0 + m) * NN + k0 + k4];
            as[k4 + 0][m] = v.x; as[k4 + 1][m] = v.y;
            as[k4 + 2][m] = v.z; as[k4 + 3][m] = v.w;
        }
        {
            int kr = tid >> 4;
            int c4 = (tid & 15) * 4;
            *(float4*)&ws[kr][c4] = *(const float4*)&Wout[(size_t)(k0 + kr) * OO + c0 + c4];
        }
        __syncthreads();
        #pragma unroll
        for (int k = 0; k < 16; k++) {
            float4 a = *(const float4*)&as[k][r0];
            float4 w = *(const float4*)&ws[k][cc];
            acc[0][0] += a.x * w.x; acc[0][1] += a.x * w.y; acc[0][2] += a.x * w.z; acc[0][3] += a.x * w.w;
            acc[1][0] += a.y * w.x; acc[1][1] += a.y * w.y; acc[1][2] += a.y * w.z; acc[1][3] += a.y * w.w;
            acc[2][0] += a.z * w.x; acc[2][1] += a.z * w.y; acc[2][2] += a.z * w.z; acc[2][3] += a.z * w.w;
            acc[3][0] += a.w * w.x; acc[3][1] += a.w * w.y; acc[3][2] += a.w * w.z; acc[3][3] += a.w * w.w;
        }
        __syncthreads();
    }
    float4 bv = *(const float4*)&bout[c0 + cc];
    #pragma unroll
    for (int i = 0; i < 4; i++) {
        float4 v = make_float4(acc[i][0] + bv.x, acc[i][1] + bv.y,
                               acc[i][2] + bv.z, acc[i][3] + bv.w);
        *(float4*)&out[(size_t)(m0 + r0 + i) * OO + c0 + cc] = v;
    }
}

// ---------------- launch ----------------
extern "C" void kernel_launch(void* const* d_in, const int* in_sizes, int n_in,
                              void* d_out, int out_size) {
    const float* X    = (const float*)d_in[0];  // [B,T,DIN]
    const float* Win  = (const float*)d_in[1];  // [DIN,N]
    const float* W    = (const float*)d_in[2];  // [N,N]
    const float* Wout = (const float*)d_in[3];  // [N,O]
    const float* bout = (const float*)d_in[4];  // [O]

    float* s_out = (float*)d_out;                            // [B,T,N]
    float* o_out = (float*)d_out + (size_t)BB * TT * NN;     // [B,T,O]

    init_kernel<<<256, 256>>>(s_out);
    xw_kernel<<<dim3(TT - 1, 16), 256>>>(X, Win);
    rnn_kernel<<<128, 128>>>(W, s_out);
    out_kernel<<<dim3((BB * TT) / 64, OO / 64), 256>>>(s_out, Wout, bout, o_out);
}

// round 9
// speedup vs baseline: 1.2989x; 1.0456x over previous
#include <cuda_runtime.h>
#include <cuda_bf16.h>
#include <math.h>

#define TT  512
#define BB  64
#define DIN 256
#define NN  1024
#define OO  128

// ---------------- device scratch (no cudaMalloc allowed) ----------------
__device__ float    g_xw[(TT - 1) * NN * BB];   // [t][n][b], t = 0..510 feeds step t+1
__device__ float    g_sbuf[4 * NN * BB];        // 4-deep ring, transposed [n][b]
__device__ float    g_part[64 * 64 * 16];       // per-ntile k-half-0 partials (thread-mapped)
__device__ unsigned g_bar;                      // barrier arrival counter (kh1 blocks only)
__device__ unsigned g_release;                  // last released step (monotonic per launch)
__device__ unsigned g_pflag[64 * 8];            // per-ntile partial-ready flag (padded 32B)

// ---------------- acquire/release helpers ----------------
__device__ __forceinline__ unsigned ld_acq(const unsigned* p) {
    unsigned v;
    asm volatile("ld.acquire.gpu.u32 %0, [%1];" : "=r"(v) : "l"(p));
    return v;
}
__device__ __forceinline__ void st_rel(unsigned* p, unsigned v) {
    asm volatile("st.release.gpu.u32 [%0], %1;" :: "l"(p), "r"(v) : "memory");
}
// bounded-backoff spin (monotonic flag -> cannot deadlock)
__device__ __forceinline__ void wait_ge(const unsigned* p, unsigned tgt) {
    #pragma unroll 1
    for (int i = 0; i < 16; i++) {
        if (ld_acq(p) >= tgt) return;
    }
    unsigned ns = 64;
    while (ld_acq(p) < tgt) {
        __nanosleep(ns);
        if (ns < 512) ns <<= 1;
    }
}

// packed fp32x2 FMA: d = a*b + d (lane-wise fp32, exact FFMA numerics)
__device__ __forceinline__ void ffma2(unsigned long long& d,
                                      unsigned long long a, unsigned long long b) {
    asm("fma.rn.f32x2 %0, %1, %2, %0;" : "+l"(d) : "l"(a), "l"(b));
}

// ---------------- init: reset sync state, zero s[:,0,:] ----------------
__global__ void init_kernel(float* __restrict__ sout) {
    int idx = blockIdx.x * blockDim.x + threadIdx.x;
    if (idx == 0) { g_bar = 0; g_release = 0; }
    if (idx < 64 * 8) g_pflag[idx] = 0;
    if (idx < NN * BB) {
        g_sbuf[idx] = 0.0f;                          // ring slot 0 = state t=0
        int b = idx / NN, n = idx % NN;
        sout[((size_t)b * TT + 0) * NN + n] = 0.0f;  // s[:,0,:] = 0
    }
}

// ---------------- XW = X[:,t,:] @ Win, stored [t][n][b] ----------------
__global__ void xw_kernel(const float* __restrict__ X, const float* __restrict__ Win) {
    const int t  = blockIdx.x;          // 0..510
    const int c0 = blockIdx.y * 64;
    __shared__ float xs[16][BB];        // [d][b]
    __shared__ float ws[16][64];        // [d][c]
    const int tid = threadIdx.x;
    const int r0 = (tid & 15) * 4;
    const int cc = (tid >> 4) * 4;
    float acc[4][4] = {};

    for (int d0 = 0; d0 < DIN; d0 += 16) {
        {
            int b  = tid & 63;
            int d4 = (tid >> 6) * 4;
            float4 xv = *(const float4*)&X[((size_t)b * TT + t) * DIN + d0 + d4];
            xs[d4 + 0][b] = xv.x; xs[d4 + 1][b] = xv.y;
            xs[d4 + 2][b] = xv.z; xs[d4 + 3][b] = xv.w;
        }
        {
            int dr = tid >> 4;
            int c4 = (tid & 15) * 4;
            *(float4*)&ws[dr][c4] = *(const float4*)&Win[(size_t)(d0 + dr) * NN + c0 + c4];
        }
        __syncthreads();
        #pragma unroll
        for (int d = 0; d < 16; d++) {
            float4 a = *(const float4*)&xs[d][r0];
            float4 w = *(const float4*)&ws[d][cc];
            acc[0][0] += a.x * w.x; acc[0][1] += a.x * w.y; acc[0][2] += a.x * w.z; acc[0][3] += a.x * w.w;
            acc[1][0] += a.y * w.x; acc[1][1] += a.y * w.y; acc[1][2] += a.y * w.z; acc[1][3] += a.y * w.w;
            acc[2][0] += a.z * w.x; acc[2][1] += a.z * w.y; acc[2][2] += a.z * w.z; acc[2][3] += a.z * w.w;
            acc[3][0] += a.w * w.x; acc[3][1] += a.w * w.y; acc[3][2] += a.w * w.z; acc[3][3] += a.w * w.w;
        }
        __syncthreads();
    }
    #pragma unroll
    for (int j = 0; j < 4; j++) {
        float4 v = make_float4(acc[0][j], acc[1][j], acc[2][j], acc[3][j]);
        *(float4*)&g_xw[((size_t)t * NN + c0 + cc + j) * BB + r0] = v;
    }
}

// ---------------- persistent recurrence kernel (R6 topology, W resident in smem) ----------------
// 128 blocks x 128 threads, 1 block/SM. block = (ntile 0..63, khalf 0..1).
// dynamic smem: wsm float2[512*16] (64KB) | ssm float[2*32*64] (16KB) | stage float[64*20] (5KB)
#define RNN_SMEM (65536 + 16384 + 5120)

__global__ void __launch_bounds__(128, 1) rnn_kernel(const float* __restrict__ W,
                                                     float* __restrict__ sout) {
    extern __shared__ char smem_raw[];
    float2* wsm   = (float2*)smem_raw;                    // [k(512)][c(16)] dup (w,w)
    float*  ssm   = (float*)(smem_raw + 65536);           // [buf(2)][k(32)][b(64)]
    float*  stage = (float*)(smem_raw + 65536 + 16384);   // [b(64)][n_local(20)]

    const int bx    = blockIdx.x;
    const int ntile = bx >> 1;
    const int kh    = bx & 1;
    const int c0    = ntile * 16;
    const int kbase = kh * 512;
    const int tid   = threadIdx.x;
    const int r0    = (tid & 15) * 4;   // b rows (4)
    const int cc    = (tid >> 4) * 2;   // local cols (2)

    // ---- preload W slice once: 512 rows x 16 cols, duplicated pairs ----
    #pragma unroll 1
    for (int i = tid; i < 512 * 16; i += 128) {
        int k = i >> 4, c = i & 15;
        float w = W[(size_t)(kbase + k) * NN + c0 + c];
        wsm[i] = make_float2(w, w);
    }
    __syncthreads();

    for (int t = 1; t < TT; t++) {
        const float* __restrict__ sprev = &g_sbuf[((t - 1) & 3) * (NN * BB) + (size_t)kbase * BB];
        unsigned long long ap0 = 0ull, ap1 = 0ull, ap2 = 0ull, ap3 = 0ull;
        // ap0=(r0,r0+1)@c0  ap1=(r0+2,r0+3)@c0  ap2=(r0,r0+1)@c1  ap3=(r0+2,r0+3)@c1

        // prologue: load chunk 0 (32 k x 64 b = 8KB) into buf 0
        {
            const float4* sv = (const float4*)sprev;
            float4* d = (float4*)ssm;
            #pragma unroll
            for (int i = 0; i < 4; i++) d[tid + 128 * i] = sv[tid + 128 * i];
        }
        __syncthreads();

        #pragma unroll 1
        for (int kc = 0; kc < 16; kc++) {
            const int buf = kc & 1;
            float4 pfs[4];
            if (kc < 15) {
                const float4* sv = (const float4*)(sprev + (size_t)(kc + 1) * 32 * BB);
                #pragma unroll
                for (int i = 0; i < 4; i++) pfs[i] = sv[tid + 128 * i];
            }
            const float*  sb = ssm + buf * (32 * 64);
            const float2* wb = wsm + kc * (32 * 16);
            #pragma unroll
            for (int k = 0; k < 32; k++) {
                ulonglong2 a = *(const ulonglong2*)&sb[k * 64 + r0];   // (s0,s1),(s2,s3)
                ulonglong2 b = *(const ulonglong2*)&wb[k * 16 + cc];   // (w0,w0),(w1,w1)
                ffma2(ap0, a.x, b.x);
                ffma2(ap1, a.y, b.x);
                ffma2(ap2, a.x, b.y);
                ffma2(ap3, a.y, b.y);
            }
            if (kc < 15) {
                float4* d = (float4*)(ssm + (buf ^ 1) * (32 * 64));
                #pragma unroll
                for (int i = 0; i < 4; i++) d[tid + 128 * i] = pfs[i];
                __syncthreads();
            }
        }

        // unpack packed accumulators -> acc[row][col]
        float acc[4][2];
        {
            float2 u;
            u = *(float2*)&ap0; acc[0][0] = u.x; acc[1][0] = u.y;
            u = *(float2*)&ap1; acc[2][0] = u.x; acc[3][0] = u.y;
            u = *(float2*)&ap2; acc[0][1] = u.x; acc[1][1] = u.y;
            u = *(float2*)&ap3; acc[2][1] = u.x; acc[3][1] = u.y;
        }

        float* p = &g_part[(size_t)ntile * 1024 + tid * 8];
        if (kh == 0) {
            // WAR safe: release >= t-1 implies partner consumed step t-1 partials
            *(float4*)&p[0] = make_float4(acc[0][0], acc[1][0], acc[2][0], acc[3][0]);
            *(float4*)&p[4] = make_float4(acc[0][1], acc[1][1], acc[2][1], acc[3][1]);
            __threadfence();
            __syncthreads();
            if (tid == 0) st_rel(&g_pflag[ntile * 8], (unsigned)t);
        } else {
            if (tid == 0) wait_ge(&g_pflag[ntile * 8], (unsigned)t);
            __syncthreads();
            float4 p0 = *(const float4*)&p[0];
            float4 p1 = *(const float4*)&p[4];
            const float* xwp = &g_xw[((size_t)(t - 1) * NN + c0 + cc) * BB];
            float4 x0 = *(const float4*)&xwp[0 * BB + r0];
            float4 x1 = *(const float4*)&xwp[1 * BB + r0];
            float sn[4][2];
            sn[0][0] = tanhf(acc[0][0] + p0.x + x0.x);
            sn[1][0] = tanhf(acc[1][0] + p0.y + x0.y);
            sn[2][0] = tanhf(acc[2][0] + p0.z + x0.z);
            sn[3][0] = tanhf(acc[3][0] + p0.w + x0.w);
            sn[0][1] = tanhf(acc[0][1] + p1.x + x1.x);
            sn[1][1] = tanhf(acc[1][1] + p1.y + x1.y);
            sn[2][1] = tanhf(acc[2][1] + p1.z + x1.z);
            sn[3][1] = tanhf(acc[3][1] + p1.w + x1.w);
            // state ring buffer (transposed [n][b])
            float* sb = &g_sbuf[(t & 3) * (NN * BB)];
            *(float4*)&sb[(size_t)(c0 + cc + 0) * BB + r0] =
                make_float4(sn[0][0], sn[1][0], sn[2][0], sn[3][0]);
            *(float4*)&sb[(size_t)(c0 + cc + 1) * BB + r0] =
                make_float4(sn[0][1], sn[1][1], sn[2][1], sn[3][1]);
            // stage into smem for coalesced sout write
            #pragma unroll
            for (int i = 0; i < 4; i++) {
                stage[(r0 + i) * 20 + cc + 0] = sn[i][0];
                stage[(r0 + i) * 20 + cc + 1] = sn[i][1];
            }
            __syncthreads();
            if (tid < 64) {
                float* dst = &sout[((size_t)tid * TT + t) * NN + c0];
                #pragma unroll
                for (int i = 0; i < 4; i++)
                    *(float4*)&dst[i * 4] = *(const float4*)&stage[tid * 20 + i * 4];
            }
            __threadfence();
            __syncthreads();
        }

        // global step barrier: kh1 blocks arrive (64 arrivals/step); all wait release
        if (tid == 0) {
            if (kh == 1) {
                unsigned v = atomicAdd(&g_bar, 1u) + 1u;
                if (v == (unsigned)(64 * t)) {
                    __threadfence();
                    st_rel(&g_release, (unsigned)t);
                }
            }
            wait_ge(&g_release, (unsigned)t);
        }
        __syncthreads();
    }
}

// ---------------- out = s @ Wout + bout ----------------
__global__ void out_kernel(const float* __restrict__ s, const float* __restrict__ Wout,
                           const float* __restrict__ bout, float* __restrict__ out) {
    const int m0 = blockIdx.x * 64;
    const int c0 = blockIdx.y * 64;
    __shared__ float as[16][64];        // [k][m]
    __shared__ float ws[16][64];        // [k][o]
    const int tid = threadIdx.x;
    const int r0 = (tid & 15) * 4;
    const int cc = (tid >> 4) * 4;
    float acc[4][4] = {};

    for (int k0 = 0; k0 < NN; k0 += 16) {
        {
            int m  = tid & 63;
            int k4 = (tid >> 6) * 4;
            float4 v = *(const float4*)&s[(size_t)(m0 + m) * NN + k0 + k4];
            as[k4 + 0][m] = v.x; as[k4 + 1][m] = v.y;
            as[k4 + 2][m] = v.z; as[k4 + 3][m] = v.w;
        }
        {
            int kr = tid >> 4;
            int c4 = (tid & 15) * 4;
            *(float4*)&ws[kr][c4] = *(const float4*)&Wout[(size_t)(k0 + kr) * OO + c0 + c4];
        }
        __syncthreads();
        #pragma unroll
        for (int k = 0; k < 16; k++) {
            float4 a = *(const float4*)&as[k][r0];
            float4 w = *(const float4*)&ws[k][cc];
            acc[0][0] += a.x * w.x; acc[0][1] += a.x * w.y; acc[0][2] += a.x * w.z; acc[0][3] += a.x * w.w;
            acc[1][0] += a.y * w.x; acc[1][1] += a.y * w.y; acc[1][2] += a.y * w.z; acc[1][3] += a.y * w.w;
            acc[2][0] += a.z * w.x; acc[2][1] += a.z * w.y; acc[2][2] += a.z * w.z; acc[2][3] += a.z * w.w;
            acc[3][0] += a.w * w.x; acc[3][1] += a.w * w.y; acc[3][2] += a.w * w.z; acc[3][3] += a.w * w.w;
        }
        __syncthreads();
    }
    float4 bv = *(const float4*)&bout[c0 + cc];
    #pragma unroll
    for (int i = 0; i < 4; i++) {
        float4 v = make_float4(acc[i][0] + bv.x, acc[i][1] + bv.y,
                               acc[i][2] + bv.z, acc[i][3] + bv.w);
        *(float4*)&out[(size_t)(m0 + r0 + i) * OO + c0 + cc] = v;
    }
}

// ---------------- launch (stateless) ----------------
extern "C" void kernel_launch(void* const* d_in, const int* in_sizes, int n_in,
                              void* d_out, int out_size) {
    const float* X    = (const float*)d_in[0];  // [B,T,DIN]
    const float* Win  = (const float*)d_in[1];  // [DIN,N]
    const float* W    = (const float*)d_in[2];  // [N,N]
    const float* Wout = (const float*)d_in[3];  // [N,O]
    const float* bout = (const float*)d_in[4];  // [O]

    float* s_out = (float*)d_out;                            // [B,T,N]
    float* o_out = (float*)d_out + (size_t)BB * TT * NN;     // [B,T,O]

    cudaFuncSetAttribute(rnn_kernel, cudaFuncAttributeMaxDynamicSharedMemorySize, RNN_SMEM);

    init_kernel<<<256, 256>>>(s_out);
    xw_kernel<<<dim3(TT - 1, 16), 256>>>(X, Win);
    rnn_kernel<<<128, 128, RNN_SMEM>>>(W, s_out);
    out_kernel<<<dim3((BB * TT) / 64, OO / 64), 256>>>(s_out, Wout, bout, o_out);
}

// round 10
// speedup vs baseline: 1.8390x; 1.4159x over previous
#include <cuda_runtime.h>
#include <cuda_bf16.h>
#include <math.h>

#define TT  512
#define BB  64
#define DIN 256
#define NN  1024
#define OO  128

// ---------------- device scratch (no cudaMalloc allowed) ----------------
__device__ float    g_xw[(TT - 1) * BB * NN];   // [t][b][n], t = 0..510 feeds step t+1
__device__ float    g_sbuf[4 * NN * BB];        // 4-deep ring, [slot][n][b]
__device__ float    g_part[16 * 8 * 4096];      // [ntile][src_kq][b*64+c]
__device__ unsigned g_cnt[16 * 8];              // per-ntile partials-published counter (32B pad)
__device__ unsigned g_done[16 * 8];             // per-ntile s-written counter (32B pad)

// ---------------- sync helpers ----------------
__device__ __forceinline__ unsigned ld_acq(const unsigned* p) {
    unsigned v;
    asm volatile("ld.acquire.gpu.u32 %0, [%1];" : "=r"(v) : "l"(p));
    return v;
}
// bounded-backoff spin on monotonic counter (cannot deadlock)
__device__ __forceinline__ void wait_ge(const unsigned* p, unsigned tgt) {
    #pragma unroll 1
    for (int i = 0; i < 16; i++) {
        if (ld_acq(p) >= tgt) return;
    }
    unsigned ns = 64;
    while (ld_acq(p) < tgt) {
        __nanosleep(ns);
        if (ns < 512) ns <<= 1;
    }
}

// packed fp32x2 FMA: d = a*b + d (lane-wise fp32, exact FFMA numerics)
__device__ __forceinline__ void ffma2(unsigned long long& d,
                                      unsigned long long a, unsigned long long b) {
    asm("fma.rn.f32x2 %0, %1, %2, %0;" : "+l"(d) : "l"(a), "l"(b));
}

// ---------------- init: reset counters, zero s[:,0,:] ----------------
__global__ void init_kernel(float* __restrict__ sout) {
    int idx = blockIdx.x * blockDim.x + threadIdx.x;
    if (idx < 16 * 8) { g_cnt[idx] = 0; g_done[idx] = 0; }
    if (idx < NN * BB) {
        g_sbuf[idx] = 0.0f;                          // ring slot 0 = state t=0
        int b = idx / NN, n = idx % NN;
        sout[((size_t)b * TT + 0) * NN + n] = 0.0f;  // s[:,0,:] = 0
    }
}

// ---------------- XW = X[:,t,:] @ Win, stored [t][b][n] ----------------
__global__ void xw_kernel(const float* __restrict__ X, const float* __restrict__ Win) {
    const int t  = blockIdx.x;          // 0..510
    const int c0 = blockIdx.y * 64;
    __shared__ float xs[16][BB];        // [d][b]
    __shared__ float ws[16][64];        // [d][c]
    const int tid = threadIdx.x;
    const int r0 = (tid & 15) * 4;
    const int cc = (tid >> 4) * 4;
    float acc[4][4] = {};

    for (int d0 = 0; d0 < DIN; d0 += 16) {
        {
            int b  = tid & 63;
            int d4 = (tid >> 6) * 4;
            float4 xv = *(const float4*)&X[((size_t)b * TT + t) * DIN + d0 + d4];
            xs[d4 + 0][b] = xv.x; xs[d4 + 1][b] = xv.y;
            xs[d4 + 2][b] = xv.z; xs[d4 + 3][b] = xv.w;
        }
        {
            int dr = tid >> 4;
            int c4 = (tid & 15) * 4;
            *(float4*)&ws[dr][c4] = *(const float4*)&Win[(size_t)(d0 + dr) * NN + c0 + c4];
        }
        __syncthreads();
        #pragma unroll
        for (int d = 0; d < 16; d++) {
            float4 a = *(const float4*)&xs[d][r0];
            float4 w = *(const float4*)&ws[d][cc];
            acc[0][0] += a.x * w.x; acc[0][1] += a.x * w.y; acc[0][2] += a.x * w.z; acc[0][3] += a.x * w.w;
            acc[1][0] += a.y * w.x; acc[1][1] += a.y * w.y; acc[1][2] += a.y * w.z; acc[1][3] += a.y * w.w;
            acc[2][0] += a.z * w.x; acc[2][1] += a.z * w.y; acc[2][2] += a.z * w.z; acc[2][3] += a.z * w.w;
            acc[3][0] += a.w * w.x; acc[3][1] += a.w * w.y; acc[3][2] += a.w * w.z; acc[3][3] += a.w * w.w;
        }
        __syncthreads();
    }
    #pragma unroll
    for (int i = 0; i < 4; i++) {
        *(float4*)&g_xw[((size_t)t * BB + r0 + i) * NN + c0 + cc] =
            make_float4(acc[i][0], acc[i][1], acc[i][2], acc[i][3]);
    }
}

// ---------------- persistent recurrence kernel ----------------
// 128 blocks x 128 threads, 1 block/SM. block = (ntile X 0..15, kq 0..7).
// Block GEMM tile: 64b x 64c over K rows [kq*128, +128). Thread tile 4b x 8c.
// All 8 blocks of a ntile publish partials; each finalizes its own 8-col slice.
// dynamic smem: wsm float[128][128] dup (64KB) | ssm float[2][32*64] (16KB)
#define RNN_SMEM (65536 + 16384)

__global__ void __launch_bounds__(128, 1) rnn_kernel(const float* __restrict__ W,
                                                     float* __restrict__ sout) {
    extern __shared__ char smem_raw[];
    float* wsm = (float*)smem_raw;                 // [k(128)][128 = 64 cols dup (w,w)]
    float* ssm = (float*)(smem_raw + 65536);       // [buf(2)][k(32)*b(64)]

    const int bx  = blockIdx.x;
    const int X   = bx >> 3;            // ntile 0..15 (64 cols)
    const int kq  = bx & 7;             // K-split 0..7 (128 rows)
    const int c0  = X * 64;
    const int kbase = kq * 128;
    const int tid = threadIdx.x;
    const int bg  = tid & 15;           // b-group: rows bg*4..+3
    const int ng  = tid >> 4;           // c-group: cols ng*8..+7

    // ---- preload W slice (128 k x 64 c), duplicated pairs ----
    #pragma unroll 1
    for (int i = tid; i < 128 * 16; i += 128) {
        int k = i >> 4, g = i & 15;     // g = group of 4 cols
        float4 w = *(const float4*)&W[(size_t)(kbase + k) * NN + c0 + g * 4];
        float* d = &wsm[k * 128 + g * 8];
        *(float4*)&d[0] = make_float4(w.x, w.x, w.y, w.y);
        *(float4*)&d[4] = make_float4(w.z, w.z, w.w, w.w);
    }
    __syncthreads();

    const unsigned n_left  = (unsigned)(2 * kq);       // ntile producing K rows [kq*128, +64)
    const unsigned n_right = (unsigned)(2 * kq + 1);   // ntile producing [kq*128+64, +64)

    for (int t = 1; t < TT; t++) {
        // ---- dependency waits (single-location polls, monotonic counters) ----
        if (tid == 0) {
            unsigned tgt = 8u * (unsigned)(t - 1);
            wait_ge(&g_done[n_left * 8],  tgt);   // our K-range inputs written
            wait_ge(&g_done[n_right * 8], tgt);
            wait_ge(&g_done[X * 8],       tgt);   // siblings consumed step t-1 partials (g_part WAR)
        }
        __syncthreads();

        const float* __restrict__ sprev =
            &g_sbuf[((t - 1) & 3) * (NN * BB) + (size_t)kbase * BB];

        unsigned long long ap[8][2];    // [col][b-pair]: ((b0,b1),(b2,b3)) per col
        #pragma unroll
        for (int j = 0; j < 8; j++) { ap[j][0] = 0ull; ap[j][1] = 0ull; }

        // prologue: chunk 0 (32 k x 64 b = 8KB) into buf 0
        {
            const float4* sv = (const float4*)sprev;
            float4* d = (float4*)ssm;
            #pragma unroll
            for (int i = 0; i < 4; i++) d[tid + 128 * i] = sv[tid + 128 * i];
        }
        __syncthreads();

        #pragma unroll 1
        for (int ch = 0; ch < 4; ch++) {
            const int buf = ch & 1;
            float4 pfs[4];
            if (ch < 3) {
                const float4* sv = (const float4*)(sprev + (size_t)(ch + 1) * 32 * BB);
                #pragma unroll
                for (int i = 0; i < 4; i++) pfs[i] = sv[tid + 128 * i];
            }
            const float* sb = ssm + buf * (32 * 64);
            const float* wr = wsm + (size_t)ch * 32 * 128 + ng * 16;
            #pragma unroll
            for (int k = 0; k < 32; k++) {
                ulonglong2 a2 = *(const ulonglong2*)&sb[k * 64 + bg * 4];  // (s0,s1),(s2,s3)
                #pragma unroll
                for (int j4 = 0; j4 < 4; j4++) {
                    ulonglong2 b2 = *(const ulonglong2*)&wr[k * 128 + j4 * 4]; // (w,w),(w',w')
                    ffma2(ap[j4 * 2 + 0][0], a2.x, b2.x);
                    ffma2(ap[j4 * 2 + 0][1], a2.y, b2.x);
                    ffma2(ap[j4 * 2 + 1][0], a2.x, b2.y);
                    ffma2(ap[j4 * 2 + 1][1], a2.y, b2.y);
                }
            }
            if (ch < 3) {
                float4* d = (float4*)(ssm + (buf ^ 1) * (32 * 64));
                #pragma unroll
                for (int i = 0; i < 4; i++) d[tid + 128 * i] = pfs[i];
                __syncthreads();
            }
        }

        // ---- publish partial tile (64x64) ----
        {
            float* p = &g_part[((size_t)X * 8 + kq) * 4096];
            #pragma unroll
            for (int i = 0; i < 4; i++) {           // b row = bg*4 + i
                int hi = i >> 1;                    // which b-pair
                float4 v0, v1;
                float2 u;
                u = *(float2*)&ap[0][hi]; v0.x = (i & 1) ? u.y : u.x;
                u = *(float2*)&ap[1][hi]; v0.y = (i & 1) ? u.y : u.x;
                u = *(float2*)&ap[2][hi]; v0.z = (i & 1) ? u.y : u.x;
                u = *(float2*)&ap[3][hi]; v0.w = (i & 1) ? u.y : u.x;
                u = *(float2*)&ap[4][hi]; v1.x = (i & 1) ? u.y : u.x;
                u = *(float2*)&ap[5][hi]; v1.y = (i & 1) ? u.y : u.x;
                u = *(float2*)&ap[6][hi]; v1.z = (i & 1) ? u.y : u.x;
                u = *(float2*)&ap[7][hi]; v1.w = (i & 1) ? u.y : u.x;
                int b = bg * 4 + i;
                *(float4*)&p[b * 64 + ng * 8 + 0] = v0;
                *(float4*)&p[b * 64 + ng * 8 + 4] = v1;
            }
        }
        __threadfence();
        __syncthreads();
        if (tid == 0) atomicAdd(&g_cnt[X * 8], 1u);

        // ---- wait all 8 partials of our ntile, then finalize our 8-col slice ----
        if (tid == 0) wait_ge(&g_cnt[X * 8], 8u * (unsigned)t);
        __syncthreads();
        {
            const int b    = tid >> 1;                       // 0..63
            const int cloc = kq * 8 + (tid & 1) * 4;         // col within ntile
            float4 sum = make_float4(0.f, 0.f, 0.f, 0.f);
            #pragma unroll
            for (int src = 0; src < 8; src++) {
                float4 v = *(const float4*)&g_part[((size_t)X * 8 + src) * 4096 + b * 64 + cloc];
                sum.x += v.x; sum.y += v.y; sum.z += v.z; sum.w += v.w;
            }
            float4 xv = *(const float4*)&g_xw[((size_t)(t - 1) * BB + b) * NN + c0 + cloc];
            float4 sn;
            sn.x = tanhf(sum.x + xv.x);
            sn.y = tanhf(sum.y + xv.y);
            sn.z = tanhf(sum.z + xv.z);
            sn.w = tanhf(sum.w + xv.w);
            // state ring [slot][n][b]
            float* sb = &g_sbuf[(t & 3) * (NN * BB)];
            sb[(size_t)(c0 + cloc + 0) * BB + b] = sn.x;
            sb[(size_t)(c0 + cloc + 1) * BB + b] = sn.y;
            sb[(size_t)(c0 + cloc + 2) * BB + b] = sn.z;
            sb[(size_t)(c0 + cloc + 3) * BB + b] = sn.w;
            // output s[b][t][n]
            *(float4*)&sout[((size_t)b * TT + t) * NN + c0 + cloc] = sn;
        }
        __threadfence();
        __syncthreads();
        if (tid == 0) atomicAdd(&g_done[X * 8], 1u);
    }
}

// ---------------- out = s @ Wout + bout ----------------
__global__ void out_kernel(const float* __restrict__ s, const float* __restrict__ Wout,
                           const float* __restrict__ bout, float* __restrict__ out) {
    const int m0 = blockIdx.x * 64;
    const int c0 = blockIdx.y * 64;
    __shared__ float as[16][64];        // [k][m]
    __shared__ float ws[16][64];        // [k][o]
    const int tid = threadIdx.x;
    const int r0 = (tid & 15) * 4;
    const int cc = (tid >> 4) * 4;
    float acc[4][4] = {};

    for (int k0 = 0; k0 < NN; k0 += 16) {
        {
            int m  = tid & 63;
            int k4 = (tid >> 6) * 4;
            float4 v = *(const float4*)&s[(size_t)(m0 + m) * NN + k0 + k4];
            as[k4 + 0][m] = v.x; as[k4 + 1][m] = v.y;
            as[k4 + 2][m] = v.z; as[k4 + 3][m] = v.w;
        }
        {
            int kr = tid >> 4;
            int c4 = (tid & 15) * 4;
            *(float4*)&ws[kr][c4] = *(const float4*)&Wout[(size_t)(k0 + kr) * OO + c0 + c4];
        }
        __syncthreads();
        #pragma unroll
        for (int k = 0; k < 16; k++) {
            float4 a = *(const float4*)&as[k][r0];
            float4 w = *(const float4*)&ws[k][cc];
            acc[0][0] += a.x * w.x; acc[0][1] += a.x * w.y; acc[0][2] += a.x * w.z; acc[0][3] += a.x * w.w;
            acc[1][0] += a.y * w.x; acc[1][1] += a.y * w.y; acc[1][2] += a.y * w.z; acc[1][3] += a.y * w.w;
            acc[2][0] += a.z * w.x; acc[2][1] += a.z * w.y; acc[2][2] += a.z * w.z; acc[2][3] += a.z * w.w;
            acc[3][0] += a.w * w.x; acc[3][1] += a.w * w.y; acc[3][2] += a.w * w.z; acc[3][3] += a.w * w.w;
        }
        __syncthreads();
    }
    float4 bv = *(const float4*)&bout[c0 + cc];
    #pragma unroll
    for (int i = 0; i < 4; i++) {
        float4 v = make_float4(acc[i][0] + bv.x, acc[i][1] + bv.y,
                               acc[i][2] + bv.z, acc[i][3] + bv.w);
        *(float4*)&out[(size_t)(m0 + r0 + i) * OO + c0 + cc] = v;
    }
}

// ---------------- launch (stateless) ----------------
extern "C" void kernel_launch(void* const* d_in, const int* in_sizes, int n_in,
                              void* d_out, int out_size) {
    const float* X    = (const float*)d_in[0];  // [B,T,DIN]
    const float* Win  = (const float*)d_in[1];  // [DIN,N]
    const float* W    = (const float*)d_in[2];  // [N,N]
    const float* Wout = (const float*)d_in[3];  // [N,O]
    const float* bout = (const float*)d_in[4];  // [O]

    float* s_out = (float*)d_out;                            // [B,T,N]
    float* o_out = (float*)d_out + (size_t)BB * TT * NN;     // [B,T,O]

    cudaFuncSetAttribute(rnn_kernel, cudaFuncAttributeMaxDynamicSharedMemorySize, RNN_SMEM);

    init_kernel<<<256, 256>>>(s_out);
    xw_kernel<<<dim3(TT - 1, 16), 256>>>(X, Win);
    rnn_kernel<<<128, 128, RNN_SMEM>>>(W, s_out);
    out_kernel<<<dim3((BB * TT) / 64, OO / 64), 256>>>(s_out, Wout, bout, o_out);
}